// round 1
// baseline (speedup 1.0000x reference)
#include <cuda_runtime.h>
#include <math.h>

// Problem constants
#define BB   4
#define SS   2048
#define DD   1024
#define HH   16
#define DK   64
#define MROWS (BB * SS)   // 8192

// Scratch (device globals; allocations are forbidden)
__device__ float g_Qh[BB * HH * SS * DK];   // 32 MB, [B,H,S,DK]
__device__ float g_Kh[BB * HH * SS * DK];   // 32 MB
__device__ float g_Vh[BB * HH * SS * DK];   // 32 MB
__device__ float g_Oc[MROWS * DD];          // 32 MB, [B,S,D] attention output

// ---------------------------------------------------------------------------
// SGEMM 128x128x8 tile, 256 threads, 8x8 per thread.
// C = A[M=8192, K=1024] @ W[K=1024, N=1024] + bias
// Used twice: QKV projection (head-split epilogue) and output projection.
// ---------------------------------------------------------------------------

// Fused QKV projection: blockIdx.z in {0,1,2} selects (x, w, bias, out).
__global__ __launch_bounds__(256, 2)
void qkv_gemm(const float* __restrict__ xq, const float* __restrict__ xk,
              const float* __restrict__ xv,
              const float* __restrict__ wq, const float* __restrict__ wk,
              const float* __restrict__ wv,
              const float* __restrict__ bq, const float* __restrict__ bk,
              const float* __restrict__ bv)
{
    const float* X; const float* W; const float* bias; float* O;
    if (blockIdx.z == 0)      { X = xq; W = wq; bias = bq; O = g_Qh; }
    else if (blockIdx.z == 1) { X = xk; W = wk; bias = bk; O = g_Kh; }
    else                      { X = xv; W = wv; bias = bv; O = g_Vh; }

    __shared__ float As[8][128];
    __shared__ float Bs[8][128];

    const int tid = threadIdx.x;
    const int tx = tid & 15;      // 0..15
    const int ty = tid >> 4;      // 0..15
    const int mBase = blockIdx.x * 128;
    const int nBase = blockIdx.y * 128;

    // Global load mapping
    const int aRow = tid >> 1;          // 0..127
    const int aCol = (tid & 1) * 4;     // 0 or 4
    const int bRow = tid >> 5;          // 0..7
    const int bCol = (tid & 31) * 4;    // 0..124

    const float* Aptr = X + (size_t)(mBase + aRow) * DD + aCol;
    const float* Bptr = W + (size_t)bRow * DD + nBase + bCol;

    float acc[8][8];
    #pragma unroll
    for (int i = 0; i < 8; i++)
        #pragma unroll
        for (int j = 0; j < 8; j++) acc[i][j] = 0.f;

    for (int k0 = 0; k0 < DD; k0 += 8) {
        float4 av  = *(const float4*)(Aptr + k0);
        float4 bv4 = *(const float4*)(Bptr + (size_t)k0 * DD);
        As[aCol + 0][aRow] = av.x;
        As[aCol + 1][aRow] = av.y;
        As[aCol + 2][aRow] = av.z;
        As[aCol + 3][aRow] = av.w;
        *(float4*)&Bs[bRow][bCol] = bv4;
        __syncthreads();

        #pragma unroll
        for (int kk = 0; kk < 8; kk++) {
            float a[8], bv[8];
            *(float4*)&a[0]  = *(const float4*)&As[kk][ty * 4];
            *(float4*)&a[4]  = *(const float4*)&As[kk][64 + ty * 4];
            *(float4*)&bv[0] = *(const float4*)&Bs[kk][tx * 4];
            *(float4*)&bv[4] = *(const float4*)&Bs[kk][64 + tx * 4];
            #pragma unroll
            for (int i = 0; i < 8; i++)
                #pragma unroll
                for (int j = 0; j < 8; j++)
                    acc[i][j] += a[i] * bv[j];
        }
        __syncthreads();
    }

    // Epilogue: add bias, scatter to head-split layout [B,H,S,DK]
    #pragma unroll
    for (int i = 0; i < 8; i++) {
        const int m = mBase + ((i < 4) ? (ty * 4 + i) : (64 + ty * 4 + (i - 4)));
        const int b = m >> 11;          // m / 2048
        const int s = m & 2047;
        #pragma unroll
        for (int j = 0; j < 8; j++) {
            const int n  = nBase + ((j < 4) ? (tx * 4 + j) : (64 + tx * 4 + (j - 4)));
            const int h  = n >> 6;
            const int dk = n & 63;
            O[(((size_t)(b * HH + h)) * SS + s) * DK + dk] = acc[i][j] + bias[n];
        }
    }
}

// Output projection: d_out = g_Oc @ wo + bo, plain row-major store.
__global__ __launch_bounds__(256, 2)
void out_gemm(const float* __restrict__ W, const float* __restrict__ bias,
              float* __restrict__ Out)
{
    __shared__ float As[8][128];
    __shared__ float Bs[8][128];

    const int tid = threadIdx.x;
    const int tx = tid & 15;
    const int ty = tid >> 4;
    const int mBase = blockIdx.x * 128;
    const int nBase = blockIdx.y * 128;

    const int aRow = tid >> 1;
    const int aCol = (tid & 1) * 4;
    const int bRow = tid >> 5;
    const int bCol = (tid & 31) * 4;

    const float* Aptr = g_Oc + (size_t)(mBase + aRow) * DD + aCol;
    const float* Bptr = W + (size_t)bRow * DD + nBase + bCol;

    float acc[8][8];
    #pragma unroll
    for (int i = 0; i < 8; i++)
        #pragma unroll
        for (int j = 0; j < 8; j++) acc[i][j] = 0.f;

    for (int k0 = 0; k0 < DD; k0 += 8) {
        float4 av  = *(const float4*)(Aptr + k0);
        float4 bv4 = *(const float4*)(Bptr + (size_t)k0 * DD);
        As[aCol + 0][aRow] = av.x;
        As[aCol + 1][aRow] = av.y;
        As[aCol + 2][aRow] = av.z;
        As[aCol + 3][aRow] = av.w;
        *(float4*)&Bs[bRow][bCol] = bv4;
        __syncthreads();

        #pragma unroll
        for (int kk = 0; kk < 8; kk++) {
            float a[8], bv[8];
            *(float4*)&a[0]  = *(const float4*)&As[kk][ty * 4];
            *(float4*)&a[4]  = *(const float4*)&As[kk][64 + ty * 4];
            *(float4*)&bv[0] = *(const float4*)&Bs[kk][tx * 4];
            *(float4*)&bv[4] = *(const float4*)&Bs[kk][64 + tx * 4];
            #pragma unroll
            for (int i = 0; i < 8; i++)
                #pragma unroll
                for (int j = 0; j < 8; j++)
                    acc[i][j] += a[i] * bv[j];
        }
        __syncthreads();
    }

    #pragma unroll
    for (int i = 0; i < 8; i++) {
        const int m = mBase + ((i < 4) ? (ty * 4 + i) : (64 + ty * 4 + (i - 4)));
        #pragma unroll
        for (int j = 0; j < 8; j++) {
            const int n = nBase + ((j < 4) ? (tx * 4 + j) : (64 + tx * 4 + (j - 4)));
            Out[(size_t)m * DD + n] = acc[i][j] + bias[n];
        }
    }
}

// ---------------------------------------------------------------------------
// Flash attention, fp32. grid = (S/128, H, B), block = 128.
// Thread i owns q-row (blockIdx.x*128 + i): q[64] and acc[64] in registers.
// K/V tiles of 32 rows in smem; all compute-phase smem reads are broadcast.
// ---------------------------------------------------------------------------
__global__ __launch_bounds__(128)
void flash_attn()
{
    __shared__ float Ks[32 * 64];
    __shared__ float Vs[32 * 64];

    const int b = blockIdx.z;
    const int h = blockIdx.y;
    const int r = blockIdx.x * 128 + threadIdx.x;   // q row in [0, S)

    const size_t headBase = ((size_t)(b * HH + h)) * SS * DK;
    const float* Qp = g_Qh + headBase + (size_t)r * DK;

    float q[64];
    #pragma unroll
    for (int i = 0; i < 16; i++) {
        float4 t = ((const float4*)Qp)[i];
        q[i * 4 + 0] = t.x; q[i * 4 + 1] = t.y;
        q[i * 4 + 2] = t.z; q[i * 4 + 3] = t.w;
    }

    float acc[64];
    #pragma unroll
    for (int d = 0; d < 64; d++) acc[d] = 0.f;
    float mi = -1e30f, li = 0.f;
    const float scale = 0.125f;   // 1/sqrt(64)

    for (int t0 = 0; t0 < SS; t0 += 32) {
        __syncthreads();
        const float4* Kg = (const float4*)(g_Kh + headBase + (size_t)t0 * DK);
        const float4* Vg = (const float4*)(g_Vh + headBase + (size_t)t0 * DK);
        #pragma unroll
        for (int i = threadIdx.x; i < 32 * 16; i += 128) {
            ((float4*)Ks)[i] = Kg[i];
            ((float4*)Vs)[i] = Vg[i];
        }
        __syncthreads();

        float s[32];
        float tmax = -1e30f;
        #pragma unroll
        for (int j = 0; j < 32; j++) {
            float s0 = 0.f, s1 = 0.f, s2 = 0.f, s3 = 0.f;
            const float4* kr = (const float4*)&Ks[j * 64];
            #pragma unroll
            for (int kk = 0; kk < 16; kk++) {
                float4 kv = kr[kk];   // warp-broadcast
                s0 += q[kk * 4 + 0] * kv.x;
                s1 += q[kk * 4 + 1] * kv.y;
                s2 += q[kk * 4 + 2] * kv.z;
                s3 += q[kk * 4 + 3] * kv.w;
            }
            float sj = ((s0 + s1) + (s2 + s3)) * scale;
            s[j] = sj;
            tmax = fmaxf(tmax, sj);
        }

        const float nm   = fmaxf(mi, tmax);
        const float corr = __expf(mi - nm);   // first tile: exp(-huge) -> 0
        li *= corr;
        #pragma unroll
        for (int d = 0; d < 64; d++) acc[d] *= corr;

        #pragma unroll
        for (int j = 0; j < 32; j++) {
            const float p = __expf(s[j] - nm);
            li += p;
            const float* vr = &Vs[j * 64];
            #pragma unroll
            for (int d = 0; d < 64; d++)
                acc[d] += p * vr[d];          // vr[d] warp-broadcast
        }
        mi = nm;
    }

    const float inv = 1.f / li;
    float* Op = g_Oc + ((size_t)(b * SS + r)) * DD + h * DK;
    #pragma unroll
    for (int i = 0; i < 16; i++) {
        float4 o;
        o.x = acc[i * 4 + 0] * inv; o.y = acc[i * 4 + 1] * inv;
        o.z = acc[i * 4 + 2] * inv; o.w = acc[i * 4 + 3] * inv;
        ((float4*)Op)[i] = o;
    }
}

// ---------------------------------------------------------------------------
extern "C" void kernel_launch(void* const* d_in, const int* in_sizes, int n_in,
                              void* d_out, int out_size)
{
    const float* q  = (const float*)d_in[0];
    const float* k  = (const float*)d_in[1];
    const float* v  = (const float*)d_in[2];
    const float* wq = (const float*)d_in[3];
    const float* bq = (const float*)d_in[4];
    const float* wk = (const float*)d_in[5];
    const float* bk = (const float*)d_in[6];
    const float* wv = (const float*)d_in[7];
    const float* bv = (const float*)d_in[8];
    const float* wo = (const float*)d_in[9];
    const float* bo = (const float*)d_in[10];
    float* out = (float*)d_out;

    // 1) QKV projections (fused over blockIdx.z), head-split scatter
    qkv_gemm<<<dim3(MROWS / 128, DD / 128, 3), 256>>>(q, k, v, wq, wk, wv, bq, bk, bv);

    // 2) Flash attention per (b, h), 128 q-rows per CTA
    flash_attn<<<dim3(SS / 128, HH, BB), 128>>>();

    // 3) Output projection + bias
    out_gemm<<<dim3(MROWS / 128, DD / 128), 256>>>(wo, bo, out);
}

// round 3
// speedup vs baseline: 1.2286x; 1.2286x over previous
#include <cuda_runtime.h>
#include <cuda_bf16.h>
#include <math.h>
#include <stdint.h>

// Problem constants
#define BB   4
#define SS   2048
#define DD   1024
#define HH   16
#define DK   64
#define MROWS (BB * SS)   // 8192

// ---------------------------------------------------------------------------
// Device scratch (allocations forbidden -> __device__ globals)
// ---------------------------------------------------------------------------
__device__ __nv_bfloat16 g_Ahi[3 * MROWS * DD];   // q,k,v activations, hi
__device__ __nv_bfloat16 g_Alo[3 * MROWS * DD];   // lo
__device__ __nv_bfloat16 g_Wthi[4 * DD * DD];     // wq,wk,wv,wo transposed [N][K], hi
__device__ __nv_bfloat16 g_Wtlo[4 * DD * DD];     // lo
__device__ float g_QKVh[3 * BB * HH * SS * DK];   // head-split Q,K,V fp32
__device__ float g_Oc[MROWS * DD];                // attention output [B,S,D] fp32
__device__ __nv_bfloat16 g_Ohi[MROWS * DD];       // attn output split for O-proj
__device__ __nv_bfloat16 g_Olo[MROWS * DD];

// ---------------------------------------------------------------------------
// PTX helpers (all base-target sm_80+ features; NO 'a'-gated instructions)
// ---------------------------------------------------------------------------
__device__ __forceinline__ uint32_t smem_u32(const void* p) {
    uint32_t a;
    asm("{ .reg .u64 t; cvta.to.shared.u64 t, %1; cvt.u32.u64 %0, t; }" : "=r"(a) : "l"(p));
    return a;
}
__device__ __forceinline__ void cp_async16(uint32_t s, const void* g) {
    asm volatile("cp.async.cg.shared.global [%0], [%1], 16;" :: "r"(s), "l"(g));
}
__device__ __forceinline__ void cp_commit() {
    asm volatile("cp.async.commit_group;" ::: "memory");
}
template <int N>
__device__ __forceinline__ void cp_wait() {
    asm volatile("cp.async.wait_group %0;" :: "n"(N) : "memory");
}
__device__ __forceinline__ void ldsm4(uint32_t* r, uint32_t a) {
    asm volatile("ldmatrix.sync.aligned.m8n8.x4.shared.b16 {%0,%1,%2,%3}, [%4];"
                 : "=r"(r[0]), "=r"(r[1]), "=r"(r[2]), "=r"(r[3]) : "r"(a));
}
__device__ __forceinline__ void mma16816(float* d, const uint32_t* a, const uint32_t* b) {
    asm volatile(
        "mma.sync.aligned.m16n8k16.row.col.f32.bf16.bf16.f32 "
        "{%0,%1,%2,%3}, {%4,%5,%6,%7}, {%8,%9}, {%0,%1,%2,%3};"
        : "+f"(d[0]), "+f"(d[1]), "+f"(d[2]), "+f"(d[3])
        : "r"(a[0]), "r"(a[1]), "r"(a[2]), "r"(a[3]), "r"(b[0]), "r"(b[1]));
}

// ---------------------------------------------------------------------------
// Conversion kernels: fp32 -> bf16 hi/lo split
// ---------------------------------------------------------------------------
__global__ void convert_act(const float* __restrict__ x0, const float* __restrict__ x1,
                            const float* __restrict__ x2)
{
    const int z = blockIdx.y;
    const float* x = (z == 0) ? x0 : (z == 1) ? x1 : x2;
    __nv_bfloat16* hi = g_Ahi + (size_t)z * MROWS * DD;
    __nv_bfloat16* lo = g_Alo + (size_t)z * MROWS * DD;

    const size_t i = (size_t)blockIdx.x * blockDim.x + threadIdx.x;   // float4 index
    float4 v = ((const float4*)x)[i];
    float f[4] = {v.x, v.y, v.z, v.w};
    __nv_bfloat16 h[4], l[4];
    #pragma unroll
    for (int j = 0; j < 4; j++) {
        h[j] = __float2bfloat16(f[j]);
        l[j] = __float2bfloat16(f[j] - __bfloat162float(h[j]));
    }
    ((__nv_bfloat162*)hi)[2 * i + 0] = __nv_bfloat162(h[0], h[1]);
    ((__nv_bfloat162*)hi)[2 * i + 1] = __nv_bfloat162(h[2], h[3]);
    ((__nv_bfloat162*)lo)[2 * i + 0] = __nv_bfloat162(l[0], l[1]);
    ((__nv_bfloat162*)lo)[2 * i + 1] = __nv_bfloat162(l[2], l[3]);
}

__global__ void convert_oc()
{
    const size_t i = (size_t)blockIdx.x * blockDim.x + threadIdx.x;
    float4 v = ((const float4*)g_Oc)[i];
    float f[4] = {v.x, v.y, v.z, v.w};
    __nv_bfloat16 h[4], l[4];
    #pragma unroll
    for (int j = 0; j < 4; j++) {
        h[j] = __float2bfloat16(f[j]);
        l[j] = __float2bfloat16(f[j] - __bfloat162float(h[j]));
    }
    ((__nv_bfloat162*)g_Ohi)[2 * i + 0] = __nv_bfloat162(h[0], h[1]);
    ((__nv_bfloat162*)g_Ohi)[2 * i + 1] = __nv_bfloat162(h[2], h[3]);
    ((__nv_bfloat162*)g_Olo)[2 * i + 0] = __nv_bfloat162(l[0], l[1]);
    ((__nv_bfloat162*)g_Olo)[2 * i + 1] = __nv_bfloat162(l[2], l[3]);
}

// Weight transpose + split: Wt[n][k] = w[k][n]
__global__ void convert_wt(const float* __restrict__ w0, const float* __restrict__ w1,
                           const float* __restrict__ w2, const float* __restrict__ w3)
{
    __shared__ float t[32][33];
    const int z = blockIdx.z;
    const float* w = (z == 0) ? w0 : (z == 1) ? w1 : (z == 2) ? w2 : w3;
    const int nb = blockIdx.x * 32;
    const int kb = blockIdx.y * 32;

    for (int i = threadIdx.y; i < 32; i += 8)
        t[i][threadIdx.x] = w[(size_t)(kb + i) * DD + nb + threadIdx.x];
    __syncthreads();

    __nv_bfloat16* hi = g_Wthi + (size_t)z * DD * DD;
    __nv_bfloat16* lo = g_Wtlo + (size_t)z * DD * DD;
    for (int i = threadIdx.y; i < 32; i += 8) {
        float v = t[threadIdx.x][i];
        __nv_bfloat16 h = __float2bfloat16(v);
        __nv_bfloat16 l = __float2bfloat16(v - __bfloat162float(h));
        size_t o = (size_t)(nb + i) * DD + kb + threadIdx.x;
        hi[o] = h;
        lo[o] = l;
    }
}

// ---------------------------------------------------------------------------
// HMMA (mma.sync) bf16x3 GEMM: C[8192,1024] = A @ W^T + bias
// CTA 128x128, K-chunk 32, 8 warps (warp tile 32x64), cp.async double buffer.
// Smem plane: 128 rows x 80B (32 bf16 + 16B pad) -> conflict-free ldmatrix.
// mode 0: QKV (z selects tensor; epilogue scatters to [B,H,S,DK] in g_QKVh)
// mode 1: O-proj (reads g_Ohi/g_Olo, writes row-major to outExt)
// ---------------------------------------------------------------------------
#define PLANE_BYTES 10240           // 128 * 80
#define BUF_BYTES   (4 * PLANE_BYTES)
#define GEMM_SMEM   (2 * BUF_BYTES) // 81920

__global__ __launch_bounds__(256, 1)
void gemm_tc(const float* __restrict__ bias0, const float* __restrict__ bias1,
             const float* __restrict__ bias2, float* __restrict__ outExt, int mode)
{
    extern __shared__ __align__(128) char smem[];
    const uint32_t smemA = smem_u32(smem);

    const int tid  = threadIdx.x;
    const int wid  = tid >> 5;
    const int lane = tid & 31;
    const int wm   = wid >> 1;       // 0..3 (M)
    const int wn   = wid & 1;        // 0..1 (N)
    const int z    = blockIdx.z;
    const int mBase = blockIdx.x * 128;
    const int nBase = blockIdx.y * 128;

    const __nv_bfloat16* Ahi = (mode == 0) ? (g_Ahi + (size_t)z * MROWS * DD) : g_Ohi;
    const __nv_bfloat16* Alo = (mode == 0) ? (g_Alo + (size_t)z * MROWS * DD) : g_Olo;
    const int widx = (mode == 0) ? z : 3;
    const __nv_bfloat16* Whi = g_Wthi + (size_t)widx * DD * DD;
    const __nv_bfloat16* Wlo = g_Wtlo + (size_t)widx * DD * DD;
    const float* bias = (z == 0) ? bias0 : (z == 1) ? bias1 : bias2;
    float* outp = (mode == 0) ? (g_QKVh + (size_t)z * BB * HH * SS * DK) : outExt;

    const __nv_bfloat16* srcs[4] = {Ahi, Alo, Whi, Wlo};

    // ---- async loader: 4 planes x 128 rows x 32 bf16 (2048 x 16B) ----
    auto load_chunk = [&](int buf, int k0) {
        char* bb = smem + buf * BUF_BYTES;
        #pragma unroll
        for (int it = 0; it < 8; it++) {
            const int idx = it * 256 + tid;      // 0..2047
            const int p   = idx >> 9;
            const int r   = idx & 511;
            const int row = r >> 2;
            const int seg = r & 3;
            const int rowBase = (p < 2) ? mBase : nBase;
            const __nv_bfloat16* g = srcs[p] + (size_t)(rowBase + row) * DD + k0 + seg * 8;
            cp_async16(smem_u32(bb + p * PLANE_BYTES + row * 80 + seg * 16), g);
        }
    };

    float acc[2][8][4];
    #pragma unroll
    for (int t = 0; t < 2; t++)
        #pragma unroll
        for (int n = 0; n < 8; n++)
            #pragma unroll
            for (int j = 0; j < 4; j++) acc[t][n][j] = 0.f;

    // per-lane ldmatrix address components
    const int aRow = lane & 15;
    const int aCol = (lane >> 4) * 16;
    const int bRow = (lane & 7) + ((lane >> 4) << 3);
    const int bCol = ((lane >> 3) & 1) * 16;

    const int NC = DD / 32;   // 32 chunks

    load_chunk(0, 0);
    cp_commit();

    for (int c = 0; c < NC; c++) {
        const int buf = c & 1;
        if (c + 1 < NC) {
            load_chunk(buf ^ 1, (c + 1) * 32);
            cp_commit();
            cp_wait<1>();
        } else {
            cp_wait<0>();
        }
        __syncthreads();

        const uint32_t base = smemA + buf * BUF_BYTES;
        #pragma unroll
        for (int s = 0; s < 2; s++) {
            uint32_t ah[2][4], al[2][4], bh[8][2], bl[8][2];
            #pragma unroll
            for (int t = 0; t < 2; t++) {
                const uint32_t addr = base + (wm * 32 + t * 16 + aRow) * 80 + s * 32 + aCol;
                ldsm4(ah[t], addr);
                ldsm4(al[t], addr + PLANE_BYTES);
            }
            #pragma unroll
            for (int bt = 0; bt < 4; bt++) {
                const uint32_t addr = base + 2 * PLANE_BYTES
                                    + (wn * 64 + bt * 16 + bRow) * 80 + s * 32 + bCol;
                uint32_t r4[4];
                ldsm4(r4, addr);
                bh[bt * 2][0] = r4[0]; bh[bt * 2][1] = r4[1];
                bh[bt * 2 + 1][0] = r4[2]; bh[bt * 2 + 1][1] = r4[3];
                ldsm4(r4, addr + PLANE_BYTES);
                bl[bt * 2][0] = r4[0]; bl[bt * 2][1] = r4[1];
                bl[bt * 2 + 1][0] = r4[2]; bl[bt * 2 + 1][1] = r4[3];
            }
            #pragma unroll
            for (int t = 0; t < 2; t++)
                #pragma unroll
                for (int n = 0; n < 8; n++) {
                    mma16816(acc[t][n], ah[t], bh[n]);   // hi*hi
                    mma16816(acc[t][n], ah[t], bl[n]);   // hi*lo
                    mma16816(acc[t][n], al[t], bh[n]);   // lo*hi
                }
        }
        __syncthreads();
    }

    // ---- epilogue: bias add + store ----
    const int rBase = mBase + wm * 32 + (lane >> 2);
    const int cBase = nBase + wn * 64 + (lane & 3) * 2;
    #pragma unroll
    for (int t = 0; t < 2; t++) {
        #pragma unroll
        for (int n = 0; n < 8; n++) {
            const int col = cBase + n * 8;
            const float b0v = bias[col];
            const float b1v = bias[col + 1];
            #pragma unroll
            for (int half = 0; half < 2; half++) {
                const int row = rBase + t * 16 + half * 8;
                float2 v;
                v.x = acc[t][n][half * 2 + 0] + b0v;
                v.y = acc[t][n][half * 2 + 1] + b1v;
                if (mode == 0) {
                    const int b = row >> 11;
                    const int s = row & 2047;
                    const int h = col >> 6;
                    const int dk = col & 63;
                    *(float2*)&outp[(((size_t)(b * HH + h)) * SS + s) * DK + dk] = v;
                } else {
                    *(float2*)&outp[(size_t)row * DD + col] = v;
                }
            }
        }
    }
}

// ---------------------------------------------------------------------------
// Flash attention, fp32 SIMT (unchanged). grid=(S/128, H, B), block=128
// ---------------------------------------------------------------------------
__global__ __launch_bounds__(128)
void flash_attn()
{
    __shared__ float Ks[32 * 64];
    __shared__ float Vs[32 * 64];

    const int b = blockIdx.z;
    const int h = blockIdx.y;
    const int r = blockIdx.x * 128 + threadIdx.x;

    const float* Qh = g_QKVh;
    const float* Kh = g_QKVh + (size_t)BB * HH * SS * DK;
    const float* Vh = g_QKVh + (size_t)2 * BB * HH * SS * DK;
    const size_t headBase = ((size_t)(b * HH + h)) * SS * DK;
    const float* Qp = Qh + headBase + (size_t)r * DK;

    float q[64];
    #pragma unroll
    for (int i = 0; i < 16; i++) {
        float4 t = ((const float4*)Qp)[i];
        q[i * 4 + 0] = t.x; q[i * 4 + 1] = t.y;
        q[i * 4 + 2] = t.z; q[i * 4 + 3] = t.w;
    }

    float acc[64];
    #pragma unroll
    for (int d = 0; d < 64; d++) acc[d] = 0.f;
    float mi = -1e30f, li = 0.f;
    const float scale = 0.125f;

    for (int t0 = 0; t0 < SS; t0 += 32) {
        __syncthreads();
        const float4* Kg = (const float4*)(Kh + headBase + (size_t)t0 * DK);
        const float4* Vg = (const float4*)(Vh + headBase + (size_t)t0 * DK);
        #pragma unroll
        for (int i = threadIdx.x; i < 32 * 16; i += 128) {
            ((float4*)Ks)[i] = Kg[i];
            ((float4*)Vs)[i] = Vg[i];
        }
        __syncthreads();

        float s[32];
        float tmax = -1e30f;
        #pragma unroll
        for (int j = 0; j < 32; j++) {
            float s0 = 0.f, s1 = 0.f, s2 = 0.f, s3 = 0.f;
            const float4* kr = (const float4*)&Ks[j * 64];
            #pragma unroll
            for (int kk = 0; kk < 16; kk++) {
                float4 kv = kr[kk];
                s0 += q[kk * 4 + 0] * kv.x;
                s1 += q[kk * 4 + 1] * kv.y;
                s2 += q[kk * 4 + 2] * kv.z;
                s3 += q[kk * 4 + 3] * kv.w;
            }
            float sj = ((s0 + s1) + (s2 + s3)) * scale;
            s[j] = sj;
            tmax = fmaxf(tmax, sj);
        }

        const float nm   = fmaxf(mi, tmax);
        const float corr = __expf(mi - nm);
        li *= corr;
        #pragma unroll
        for (int d = 0; d < 64; d++) acc[d] *= corr;

        #pragma unroll
        for (int j = 0; j < 32; j++) {
            const float p = __expf(s[j] - nm);
            li += p;
            const float* vr = &Vs[j * 64];
            #pragma unroll
            for (int d = 0; d < 64; d++)
                acc[d] += p * vr[d];
        }
        mi = nm;
    }

    const float inv = 1.f / li;
    float* Op = g_Oc + ((size_t)(b * SS + r)) * DD + h * DK;
    #pragma unroll
    for (int i = 0; i < 16; i++) {
        float4 o;
        o.x = acc[i * 4 + 0] * inv; o.y = acc[i * 4 + 1] * inv;
        o.z = acc[i * 4 + 2] * inv; o.w = acc[i * 4 + 3] * inv;
        ((float4*)Op)[i] = o;
    }
}

// ---------------------------------------------------------------------------
extern "C" void kernel_launch(void* const* d_in, const int* in_sizes, int n_in,
                              void* d_out, int out_size)
{
    const float* q  = (const float*)d_in[0];
    const float* k  = (const float*)d_in[1];
    const float* v  = (const float*)d_in[2];
    const float* wq = (const float*)d_in[3];
    const float* bq = (const float*)d_in[4];
    const float* wk = (const float*)d_in[5];
    const float* bk = (const float*)d_in[6];
    const float* wv = (const float*)d_in[7];
    const float* bv = (const float*)d_in[8];
    const float* wo = (const float*)d_in[9];
    const float* bo = (const float*)d_in[10];
    float* out = (float*)d_out;

    cudaFuncSetAttribute(gemm_tc, cudaFuncAttributeMaxDynamicSharedMemorySize, GEMM_SMEM);

    // 1) Split inputs to bf16 hi/lo; transpose+split weights
    convert_act<<<dim3(MROWS * DD / 4 / 256, 3), 256>>>(q, k, v);
    convert_wt<<<dim3(32, 32, 4), dim3(32, 8)>>>(wq, wk, wv, wo);

    // 2) QKV projections on HMMA tensor cores (bf16x3), head-split epilogue
    gemm_tc<<<dim3(MROWS / 128, DD / 128, 3), 256, GEMM_SMEM>>>(bq, bk, bv, nullptr, 0);

    // 3) Flash attention (fp32 SIMT)
    flash_attn<<<dim3(SS / 128, HH, BB), 128>>>();

    // 4) Split attention output, O projection on HMMA
    convert_oc<<<MROWS * DD / 4 / 256, 256>>>();
    gemm_tc<<<dim3(MROWS / 128, DD / 128, 1), 256, GEMM_SMEM>>>(bo, bo, bo, out, 1);
}

// round 4
// speedup vs baseline: 2.9517x; 2.4025x over previous
#include <cuda_runtime.h>
#include <cuda_bf16.h>
#include <math.h>
#include <stdint.h>

// Problem constants
#define BB   4
#define SS   2048
#define DD   1024
#define HH   16
#define DK   64
#define MROWS (BB * SS)   // 8192

// 0.125 * log2(e): folds softmax scale + base-2 exp into Q projection
#define QSCALE 0.18033688011112042f

// ---------------------------------------------------------------------------
// Device scratch (allocations forbidden -> __device__ globals)
// ---------------------------------------------------------------------------
__device__ __nv_bfloat16 g_Ahi[3 * MROWS * DD];   // q,k,v activations, hi
__device__ __nv_bfloat16 g_Alo[3 * MROWS * DD];   // lo
__device__ __nv_bfloat16 g_Wthi[4 * DD * DD];     // weights transposed [N][K], hi
__device__ __nv_bfloat16 g_Wtlo[4 * DD * DD];     // lo
__device__ __nv_bfloat16 g_Ph[3 * BB * HH * SS * DK];  // head-split Q,K,V bf16 hi
__device__ __nv_bfloat16 g_Pl[3 * BB * HH * SS * DK];  // lo
__device__ __nv_bfloat16 g_Ohi[MROWS * DD];       // attn output split for O-proj
__device__ __nv_bfloat16 g_Olo[MROWS * DD];

// ---------------------------------------------------------------------------
// PTX helpers (base-target sm_80+; nothing 'a'-gated)
// ---------------------------------------------------------------------------
__device__ __forceinline__ uint32_t smem_u32(const void* p) {
    uint32_t a;
    asm("{ .reg .u64 t; cvta.to.shared.u64 t, %1; cvt.u32.u64 %0, t; }" : "=r"(a) : "l"(p));
    return a;
}
__device__ __forceinline__ void cp_async16(uint32_t s, const void* g) {
    asm volatile("cp.async.cg.shared.global [%0], [%1], 16;" :: "r"(s), "l"(g));
}
__device__ __forceinline__ void cp_commit() {
    asm volatile("cp.async.commit_group;" ::: "memory");
}
template <int N>
__device__ __forceinline__ void cp_wait() {
    asm volatile("cp.async.wait_group %0;" :: "n"(N) : "memory");
}
__device__ __forceinline__ void ldsm4(uint32_t* r, uint32_t a) {
    asm volatile("ldmatrix.sync.aligned.m8n8.x4.shared.b16 {%0,%1,%2,%3}, [%4];"
                 : "=r"(r[0]), "=r"(r[1]), "=r"(r[2]), "=r"(r[3]) : "r"(a));
}
__device__ __forceinline__ void ldsm4t(uint32_t* r, uint32_t a) {
    asm volatile("ldmatrix.sync.aligned.m8n8.x4.trans.shared.b16 {%0,%1,%2,%3}, [%4];"
                 : "=r"(r[0]), "=r"(r[1]), "=r"(r[2]), "=r"(r[3]) : "r"(a));
}
__device__ __forceinline__ void mma16816(float* d, const uint32_t* a, const uint32_t* b) {
    asm volatile(
        "mma.sync.aligned.m16n8k16.row.col.f32.bf16.bf16.f32 "
        "{%0,%1,%2,%3}, {%4,%5,%6,%7}, {%8,%9}, {%0,%1,%2,%3};"
        : "+f"(d[0]), "+f"(d[1]), "+f"(d[2]), "+f"(d[3])
        : "r"(a[0]), "r"(a[1]), "r"(a[2]), "r"(a[3]), "r"(b[0]), "r"(b[1]));
}
__device__ __forceinline__ uint32_t packbf(float x, float y) {
    __nv_bfloat162 t = __floats2bfloat162_rn(x, y);
    return *(uint32_t*)&t;
}

// ---------------------------------------------------------------------------
// Conversions
// ---------------------------------------------------------------------------
__global__ void convert_act(const float* __restrict__ x0, const float* __restrict__ x1,
                            const float* __restrict__ x2)
{
    const int z = blockIdx.y;
    const float* x = (z == 0) ? x0 : (z == 1) ? x1 : x2;
    __nv_bfloat16* hi = g_Ahi + (size_t)z * MROWS * DD;
    __nv_bfloat16* lo = g_Alo + (size_t)z * MROWS * DD;

    const size_t i = (size_t)blockIdx.x * blockDim.x + threadIdx.x;
    float4 v = ((const float4*)x)[i];
    float f[4] = {v.x, v.y, v.z, v.w};
    __nv_bfloat16 h[4], l[4];
    #pragma unroll
    for (int j = 0; j < 4; j++) {
        h[j] = __float2bfloat16(f[j]);
        l[j] = __float2bfloat16(f[j] - __bfloat162float(h[j]));
    }
    ((__nv_bfloat162*)hi)[2 * i + 0] = __nv_bfloat162(h[0], h[1]);
    ((__nv_bfloat162*)hi)[2 * i + 1] = __nv_bfloat162(h[2], h[3]);
    ((__nv_bfloat162*)lo)[2 * i + 0] = __nv_bfloat162(l[0], l[1]);
    ((__nv_bfloat162*)lo)[2 * i + 1] = __nv_bfloat162(l[2], l[3]);
}

__global__ void convert_wt(const float* __restrict__ w0, const float* __restrict__ w1,
                           const float* __restrict__ w2, const float* __restrict__ w3)
{
    __shared__ float t[32][33];
    const int z = blockIdx.z;
    const float* w = (z == 0) ? w0 : (z == 1) ? w1 : (z == 2) ? w2 : w3;
    const int nb = blockIdx.x * 32;
    const int kb = blockIdx.y * 32;

    for (int i = threadIdx.y; i < 32; i += 8)
        t[i][threadIdx.x] = w[(size_t)(kb + i) * DD + nb + threadIdx.x];
    __syncthreads();

    __nv_bfloat16* hi = g_Wthi + (size_t)z * DD * DD;
    __nv_bfloat16* lo = g_Wtlo + (size_t)z * DD * DD;
    for (int i = threadIdx.y; i < 32; i += 8) {
        float v = t[threadIdx.x][i];
        __nv_bfloat16 h = __float2bfloat16(v);
        __nv_bfloat16 l = __float2bfloat16(v - __bfloat162float(h));
        size_t o = (size_t)(nb + i) * DD + kb + threadIdx.x;
        hi[o] = h;
        lo[o] = l;
    }
}

// ---------------------------------------------------------------------------
// HMMA bf16x3 GEMM: CTA 128x128, K-chunk 32, 8 warps, cp.async double buffer.
// mode 0: QKV. epilogue writes bf16 hi/lo to g_Ph/g_Pl [z][B,H,S,DK];
//         z==0 (Q) additionally scaled by QSCALE.
// mode 1: O-proj. reads g_Ohi/g_Olo, fp32 row-major to outExt.
// ---------------------------------------------------------------------------
#define PLANE_BYTES 10240           // 128 * 80
#define BUF_BYTES   (4 * PLANE_BYTES)
#define GEMM_SMEM   (2 * BUF_BYTES) // 81920

__global__ __launch_bounds__(256, 1)
void gemm_tc(const float* __restrict__ bias0, const float* __restrict__ bias1,
             const float* __restrict__ bias2, float* __restrict__ outExt, int mode)
{
    extern __shared__ __align__(128) char smem[];
    const uint32_t smemA = smem_u32(smem);

    const int tid  = threadIdx.x;
    const int wid  = tid >> 5;
    const int lane = tid & 31;
    const int wm   = wid >> 1;
    const int wn   = wid & 1;
    const int z    = blockIdx.z;
    const int mBase = blockIdx.x * 128;
    const int nBase = blockIdx.y * 128;

    const __nv_bfloat16* Ahi = (mode == 0) ? (g_Ahi + (size_t)z * MROWS * DD) : g_Ohi;
    const __nv_bfloat16* Alo = (mode == 0) ? (g_Alo + (size_t)z * MROWS * DD) : g_Olo;
    const int widx = (mode == 0) ? z : 3;
    const __nv_bfloat16* Whi = g_Wthi + (size_t)widx * DD * DD;
    const __nv_bfloat16* Wlo = g_Wtlo + (size_t)widx * DD * DD;
    const float* bias = (z == 0) ? bias0 : (z == 1) ? bias1 : bias2;

    const __nv_bfloat16* srcs[4] = {Ahi, Alo, Whi, Wlo};

    auto load_chunk = [&](int buf, int k0) {
        char* bb = smem + buf * BUF_BYTES;
        #pragma unroll
        for (int it = 0; it < 8; it++) {
            const int idx = it * 256 + tid;
            const int p   = idx >> 9;
            const int r   = idx & 511;
            const int row = r >> 2;
            const int seg = r & 3;
            const int rowBase = (p < 2) ? mBase : nBase;
            const __nv_bfloat16* g = srcs[p] + (size_t)(rowBase + row) * DD + k0 + seg * 8;
            cp_async16(smem_u32(bb + p * PLANE_BYTES + row * 80 + seg * 16), g);
        }
    };

    float acc[2][8][4];
    #pragma unroll
    for (int t = 0; t < 2; t++)
        #pragma unroll
        for (int n = 0; n < 8; n++)
            #pragma unroll
            for (int j = 0; j < 4; j++) acc[t][n][j] = 0.f;

    const int aRow = lane & 15;
    const int aCol = (lane >> 4) * 16;
    const int bRow = (lane & 7) + ((lane >> 4) << 3);
    const int bCol = ((lane >> 3) & 1) * 16;

    const int NC = DD / 32;

    load_chunk(0, 0);
    cp_commit();

    for (int c = 0; c < NC; c++) {
        const int buf = c & 1;
        if (c + 1 < NC) {
            load_chunk(buf ^ 1, (c + 1) * 32);
            cp_commit();
            cp_wait<1>();
        } else {
            cp_wait<0>();
        }
        __syncthreads();

        const uint32_t base = smemA + buf * BUF_BYTES;
        #pragma unroll
        for (int s = 0; s < 2; s++) {
            uint32_t ah[2][4], al[2][4], bh[8][2], bl[8][2];
            #pragma unroll
            for (int t = 0; t < 2; t++) {
                const uint32_t addr = base + (wm * 32 + t * 16 + aRow) * 80 + s * 32 + aCol;
                ldsm4(ah[t], addr);
                ldsm4(al[t], addr + PLANE_BYTES);
            }
            #pragma unroll
            for (int bt = 0; bt < 4; bt++) {
                const uint32_t addr = base + 2 * PLANE_BYTES
                                    + (wn * 64 + bt * 16 + bRow) * 80 + s * 32 + bCol;
                uint32_t r4[4];
                ldsm4(r4, addr);
                bh[bt * 2][0] = r4[0]; bh[bt * 2][1] = r4[1];
                bh[bt * 2 + 1][0] = r4[2]; bh[bt * 2 + 1][1] = r4[3];
                ldsm4(r4, addr + PLANE_BYTES);
                bl[bt * 2][0] = r4[0]; bl[bt * 2][1] = r4[1];
                bl[bt * 2 + 1][0] = r4[2]; bl[bt * 2 + 1][1] = r4[3];
            }
            #pragma unroll
            for (int t = 0; t < 2; t++)
                #pragma unroll
                for (int n = 0; n < 8; n++) {
                    mma16816(acc[t][n], ah[t], bh[n]);
                    mma16816(acc[t][n], ah[t], bl[n]);
                    mma16816(acc[t][n], al[t], bh[n]);
                }
        }
        __syncthreads();
    }

    // ---- epilogue ----
    const int rBase = mBase + wm * 32 + (lane >> 2);
    const int cBase = nBase + wn * 64 + (lane & 3) * 2;
    const float csc = (mode == 0 && z == 0) ? QSCALE : 1.0f;
    __nv_bfloat16* ph = g_Ph + (size_t)z * BB * HH * SS * DK;
    __nv_bfloat16* pl = g_Pl + (size_t)z * BB * HH * SS * DK;

    #pragma unroll
    for (int t = 0; t < 2; t++) {
        #pragma unroll
        for (int n = 0; n < 8; n++) {
            const int col = cBase + n * 8;
            const float b0v = bias[col];
            const float b1v = bias[col + 1];
            #pragma unroll
            for (int half = 0; half < 2; half++) {
                const int row = rBase + t * 16 + half * 8;
                float v0 = (acc[t][n][half * 2 + 0] + b0v) * csc;
                float v1 = (acc[t][n][half * 2 + 1] + b1v) * csc;
                if (mode == 0) {
                    const int b = row >> 11;
                    const int s = row & 2047;
                    const int h = col >> 6;
                    const int dk = col & 63;
                    const size_t o = (((size_t)(b * HH + h)) * SS + s) * DK + dk;
                    __nv_bfloat16 h0 = __float2bfloat16(v0);
                    __nv_bfloat16 h1 = __float2bfloat16(v1);
                    *(__nv_bfloat162*)&ph[o] = __nv_bfloat162(h0, h1);
                    *(__nv_bfloat162*)&pl[o] = __nv_bfloat162(
                        __float2bfloat16(v0 - __bfloat162float(h0)),
                        __float2bfloat16(v1 - __bfloat162float(h1)));
                } else {
                    float2 v; v.x = v0; v.y = v1;
                    *(float2*)&outExt[(size_t)row * DD + col] = v;
                }
            }
        }
    }
}

// ---------------------------------------------------------------------------
// Tensor-core flash attention (bf16x3 both GEMMs).
// grid=(S/128, H, B), block=256 (8 warps, 16 q-rows each). Key tile 64.
// Smem: K/V tiles, 4 planes x 64 rows x 144B, double buffered (73728 B).
// Q staged through buf0 then register-resident.
// ---------------------------------------------------------------------------
#define ARS    144                  // attn smem row stride (bytes)
#define APLANE (64 * ARS)           // 9216
#define ABUF   (4 * APLANE)         // 36864
#define ATTN_SMEM (2 * ABUF)        // 73728

__global__ __launch_bounds__(256, 1)
void attn_tc()
{
    extern __shared__ __align__(128) char smem[];
    const uint32_t smemA = smem_u32(smem);

    const int tid  = threadIdx.x;
    const int wid  = tid >> 5;
    const int lane = tid & 31;
    const int b = blockIdx.z;
    const int h = blockIdx.y;
    const int qBase = blockIdx.x * 128;

    const size_t hb = ((size_t)(b * HH + h)) * SS * DK;
    const size_t PS = (size_t)BB * HH * SS * DK;
    const __nv_bfloat16* Qh = g_Ph + hb;
    const __nv_bfloat16* Ql = g_Pl + hb;
    const __nv_bfloat16* Kh = g_Ph + PS + hb;
    const __nv_bfloat16* Kl = g_Pl + PS + hb;
    const __nv_bfloat16* Vh = g_Ph + 2 * PS + hb;
    const __nv_bfloat16* Vl = g_Pl + 2 * PS + hb;

    // ---- stage Q (128 rows x 64 dk, hi+lo) through buf0, load to regs ----
    {
        #pragma unroll
        for (int it = 0; it < 8; it++) {
            const int idx = it * 256 + tid;        // 0..2047
            const int p   = idx >> 10;             // 0=hi 1=lo
            const int r   = idx & 1023;
            const int row = r >> 3;
            const int seg = r & 7;
            const __nv_bfloat16* g = (p ? Ql : Qh) + (size_t)(qBase + row) * DK + seg * 8;
            cp_async16(smemA + p * (128 * ARS) + row * ARS + seg * 16, g);
        }
        cp_commit();
        cp_wait<0>();
        __syncthreads();
    }

    uint32_t qh[4][4], ql[4][4];
    {
        const int aRow = lane & 15;
        const int aCol = (lane >> 4) * 16;
        #pragma unroll
        for (int s = 0; s < 4; s++) {
            const uint32_t addr = smemA + (wid * 16 + aRow) * ARS + s * 32 + aCol;
            ldsm4(qh[s], addr);
            ldsm4(ql[s], addr + 128 * ARS);
        }
    }
    __syncthreads();   // Q regs extracted; smem reusable

    // ---- K/V tile loader ----
    auto load_kv = [&](int buf, int t0) {
        char* bb = smem + buf * ABUF;
        #pragma unroll
        for (int it = 0; it < 8; it++) {
            const int idx = it * 256 + tid;        // 0..2047
            const int p   = idx >> 9;              // 0=kh 1=kl 2=vh 3=vl
            const int r   = idx & 511;
            const int row = r >> 3;
            const int seg = r & 7;
            const __nv_bfloat16* src =
                (p == 0) ? Kh : (p == 1) ? Kl : (p == 2) ? Vh : Vl;
            const __nv_bfloat16* g = src + (size_t)(t0 + row) * DK + seg * 8;
            cp_async16(smem_u32(bb + p * APLANE + row * ARS + seg * 16), g);
        }
    };

    float oacc[8][4];
    #pragma unroll
    for (int n = 0; n < 8; n++)
        #pragma unroll
        for (int j = 0; j < 4; j++) oacc[n][j] = 0.f;
    float m0 = -1e30f, m1 = -1e30f, l0 = 0.f, l1 = 0.f;

    const int bRow = (lane & 7) + ((lane >> 4) << 3);
    const int bCol = ((lane >> 3) & 1) * 16;
    const int vRow = lane & 15;
    const int vCol = (lane >> 4) * 16;

    load_kv(0, 0);
    cp_commit();

    const int NT = SS / 64;   // 32 key tiles

    for (int t = 0; t < NT; t++) {
        const int buf = t & 1;
        if (t + 1 < NT) {
            load_kv(buf ^ 1, (t + 1) * 64);
            cp_commit();
            cp_wait<1>();
        } else {
            cp_wait<0>();
        }
        __syncthreads();

        const uint32_t kbase = smemA + buf * ABUF;
        const uint32_t vbase = kbase + 2 * APLANE;

        // ---- S = Q K^T (bf16x3, base-2-log-scaled) ----
        float sc[8][4];
        #pragma unroll
        for (int n = 0; n < 8; n++)
            #pragma unroll
            for (int j = 0; j < 4; j++) sc[n][j] = 0.f;

        #pragma unroll
        for (int s = 0; s < 4; s++) {
            uint32_t bh[8][2], bl[8][2];
            #pragma unroll
            for (int bt = 0; bt < 4; bt++) {
                const uint32_t addr = kbase + (bt * 16 + bRow) * ARS + s * 32 + bCol;
                uint32_t r4[4];
                ldsm4(r4, addr);
                bh[bt * 2][0] = r4[0]; bh[bt * 2][1] = r4[1];
                bh[bt * 2 + 1][0] = r4[2]; bh[bt * 2 + 1][1] = r4[3];
                ldsm4(r4, addr + APLANE);
                bl[bt * 2][0] = r4[0]; bl[bt * 2][1] = r4[1];
                bl[bt * 2 + 1][0] = r4[2]; bl[bt * 2 + 1][1] = r4[3];
            }
            #pragma unroll
            for (int n = 0; n < 8; n++) {
                mma16816(sc[n], qh[s], bh[n]);
                mma16816(sc[n], qh[s], bl[n]);
                mma16816(sc[n], ql[s], bh[n]);
            }
        }

        // ---- online softmax (base 2) ----
        float t0v = -1e30f, t1v = -1e30f;
        #pragma unroll
        for (int n = 0; n < 8; n++) {
            t0v = fmaxf(t0v, fmaxf(sc[n][0], sc[n][1]));
            t1v = fmaxf(t1v, fmaxf(sc[n][2], sc[n][3]));
        }
        t0v = fmaxf(t0v, __shfl_xor_sync(0xffffffffu, t0v, 1));
        t0v = fmaxf(t0v, __shfl_xor_sync(0xffffffffu, t0v, 2));
        t1v = fmaxf(t1v, __shfl_xor_sync(0xffffffffu, t1v, 1));
        t1v = fmaxf(t1v, __shfl_xor_sync(0xffffffffu, t1v, 2));

        const float nm0 = fmaxf(m0, t0v);
        const float nm1 = fmaxf(m1, t1v);
        const float c0 = exp2f(m0 - nm0);
        const float c1 = exp2f(m1 - nm1);
        m0 = nm0; m1 = nm1;
        l0 *= c0;  l1 *= c1;
        #pragma unroll
        for (int n = 0; n < 8; n++) {
            oacc[n][0] *= c0; oacc[n][1] *= c0;
            oacc[n][2] *= c1; oacc[n][3] *= c1;
        }

        float rs0 = 0.f, rs1 = 0.f;
        #pragma unroll
        for (int n = 0; n < 8; n++) {
            sc[n][0] = exp2f(sc[n][0] - nm0);
            sc[n][1] = exp2f(sc[n][1] - nm0);
            sc[n][2] = exp2f(sc[n][2] - nm1);
            sc[n][3] = exp2f(sc[n][3] - nm1);
            rs0 += sc[n][0] + sc[n][1];
            rs1 += sc[n][2] + sc[n][3];
        }
        rs0 += __shfl_xor_sync(0xffffffffu, rs0, 1);
        rs0 += __shfl_xor_sync(0xffffffffu, rs0, 2);
        rs1 += __shfl_xor_sync(0xffffffffu, rs1, 1);
        rs1 += __shfl_xor_sync(0xffffffffu, rs1, 2);
        l0 += rs0; l1 += rs1;

        // ---- O += P V (bf16x3; P split hi/lo, V split hi/lo) ----
        #pragma unroll
        for (int j = 0; j < 4; j++) {
            // A-frags for keys 16j..16j+15 from sc frags 2j, 2j+1
            float p00 = sc[2*j][0],   p01 = sc[2*j][1];
            float p02 = sc[2*j][2],   p03 = sc[2*j][3];
            float p10 = sc[2*j+1][0], p11 = sc[2*j+1][1];
            float p12 = sc[2*j+1][2], p13 = sc[2*j+1][3];
            uint32_t aph[4], apl[4];
            aph[0] = packbf(p00, p01); aph[1] = packbf(p02, p03);
            aph[2] = packbf(p10, p11); aph[3] = packbf(p12, p13);
            {
                __nv_bfloat162 h0 = *(__nv_bfloat162*)&aph[0];
                __nv_bfloat162 h1 = *(__nv_bfloat162*)&aph[1];
                __nv_bfloat162 h2 = *(__nv_bfloat162*)&aph[2];
                __nv_bfloat162 h3 = *(__nv_bfloat162*)&aph[3];
                apl[0] = packbf(p00 - __bfloat162float(h0.x), p01 - __bfloat162float(h0.y));
                apl[1] = packbf(p02 - __bfloat162float(h1.x), p03 - __bfloat162float(h1.y));
                apl[2] = packbf(p10 - __bfloat162float(h2.x), p11 - __bfloat162float(h2.y));
                apl[3] = packbf(p12 - __bfloat162float(h3.x), p13 - __bfloat162float(h3.y));
            }

            uint32_t vbh[8][2], vbl[8][2];
            #pragma unroll
            for (int d = 0; d < 4; d++) {
                const uint32_t addr = vbase + (j * 16 + vRow) * ARS + d * 32 + vCol;
                uint32_t r4[4];
                ldsm4t(r4, addr);
                vbh[d * 2][0] = r4[0]; vbh[d * 2][1] = r4[1];
                vbh[d * 2 + 1][0] = r4[2]; vbh[d * 2 + 1][1] = r4[3];
                ldsm4t(r4, addr + APLANE);
                vbl[d * 2][0] = r4[0]; vbl[d * 2][1] = r4[1];
                vbl[d * 2 + 1][0] = r4[2]; vbl[d * 2 + 1][1] = r4[3];
            }
            #pragma unroll
            for (int n = 0; n < 8; n++) {
                mma16816(oacc[n], aph, vbh[n]);
                mma16816(oacc[n], aph, vbl[n]);
                mma16816(oacc[n], apl, vbh[n]);
            }
        }
        __syncthreads();
    }

    // ---- epilogue: normalize, split bf16 hi/lo, write [B,S,D] ----
    const float inv0 = 1.f / l0;
    const float inv1 = 1.f / l1;
    const int s0 = qBase + wid * 16 + (lane >> 2);
    const int s1 = s0 + 8;
    #pragma unroll
    for (int n = 0; n < 8; n++) {
        const int col = h * 64 + n * 8 + (lane & 3) * 2;
        {
            float v0 = oacc[n][0] * inv0, v1 = oacc[n][1] * inv0;
            __nv_bfloat16 h0 = __float2bfloat16(v0);
            __nv_bfloat16 h1 = __float2bfloat16(v1);
            const size_t o = ((size_t)(b * SS + s0)) * DD + col;
            *(__nv_bfloat162*)&g_Ohi[o] = __nv_bfloat162(h0, h1);
            *(__nv_bfloat162*)&g_Olo[o] = __nv_bfloat162(
                __float2bfloat16(v0 - __bfloat162float(h0)),
                __float2bfloat16(v1 - __bfloat162float(h1)));
        }
        {
            float v0 = oacc[n][2] * inv1, v1 = oacc[n][3] * inv1;
            __nv_bfloat16 h0 = __float2bfloat16(v0);
            __nv_bfloat16 h1 = __float2bfloat16(v1);
            const size_t o = ((size_t)(b * SS + s1)) * DD + col;
            *(__nv_bfloat162*)&g_Ohi[o] = __nv_bfloat162(h0, h1);
            *(__nv_bfloat162*)&g_Olo[o] = __nv_bfloat162(
                __float2bfloat16(v0 - __bfloat162float(h0)),
                __float2bfloat16(v1 - __bfloat162float(h1)));
        }
    }
}

// ---------------------------------------------------------------------------
extern "C" void kernel_launch(void* const* d_in, const int* in_sizes, int n_in,
                              void* d_out, int out_size)
{
    const float* q  = (const float*)d_in[0];
    const float* k  = (const float*)d_in[1];
    const float* v  = (const float*)d_in[2];
    const float* wq = (const float*)d_in[3];
    const float* bq = (const float*)d_in[4];
    const float* wk = (const float*)d_in[5];
    const float* bk = (const float*)d_in[6];
    const float* wv = (const float*)d_in[7];
    const float* bv = (const float*)d_in[8];
    const float* wo = (const float*)d_in[9];
    const float* bo = (const float*)d_in[10];
    float* out = (float*)d_out;

    cudaFuncSetAttribute(gemm_tc, cudaFuncAttributeMaxDynamicSharedMemorySize, GEMM_SMEM);
    cudaFuncSetAttribute(attn_tc, cudaFuncAttributeMaxDynamicSharedMemorySize, ATTN_SMEM);

    // 1) Split inputs; transpose+split weights
    convert_act<<<dim3(MROWS * DD / 4 / 256, 3), 256>>>(q, k, v);
    convert_wt<<<dim3(32, 32, 4), dim3(32, 8)>>>(wq, wk, wv, wo);

    // 2) QKV projections -> bf16 hi/lo head-split (Q pre-scaled by 0.125*log2e)
    gemm_tc<<<dim3(MROWS / 128, DD / 128, 3), 256, GEMM_SMEM>>>(bq, bk, bv, nullptr, 0);

    // 3) Tensor-core flash attention -> g_Ohi/g_Olo
    attn_tc<<<dim3(SS / 128, HH, BB), 256, ATTN_SMEM>>>();

    // 4) O projection
    gemm_tc<<<dim3(MROWS / 128, DD / 128, 1), 256, GEMM_SMEM>>>(bo, bo, bo, out, 1);
}

// round 5
// speedup vs baseline: 4.0983x; 1.3885x over previous
#include <cuda_runtime.h>
#include <cuda_fp16.h>
#include <math.h>
#include <stdint.h>

// Problem constants
#define BB   4
#define SS   2048
#define DD   1024
#define HH   16
#define DK   64
#define MROWS (BB * SS)   // 8192

// 0.125 * log2(e): folds softmax scale + base-2 exp into Q projection
#define QSCALE 0.18033688011112042f

// ---------------------------------------------------------------------------
// Device scratch (allocations forbidden -> __device__ globals)
// ---------------------------------------------------------------------------
__device__ __half g_Ahi[3 * MROWS * DD];   // q,k,v activations, fp16 hi
__device__ __half g_Alo[3 * MROWS * DD];   // fp16 lo (residual)
__device__ __half g_Wt[4 * DD * DD];       // weights transposed [N][K], single fp16
__device__ __half g_Ph[3 * BB * HH * SS * DK];  // head-split Q,K,V fp16 hi
__device__ __half g_Pl[3 * BB * HH * SS * DK];  // lo (only Q's lo is consumed)
__device__ __half g_Ohi[MROWS * DD];       // attn output split for O-proj
__device__ __half g_Olo[MROWS * DD];

// ---------------------------------------------------------------------------
// PTX helpers (base-target sm_80+; nothing 'a'-gated)
// ---------------------------------------------------------------------------
__device__ __forceinline__ uint32_t smem_u32(const void* p) {
    uint32_t a;
    asm("{ .reg .u64 t; cvta.to.shared.u64 t, %1; cvt.u32.u64 %0, t; }" : "=r"(a) : "l"(p));
    return a;
}
__device__ __forceinline__ void cp_async16(uint32_t s, const void* g) {
    asm volatile("cp.async.cg.shared.global [%0], [%1], 16;" :: "r"(s), "l"(g));
}
__device__ __forceinline__ void cp_commit() {
    asm volatile("cp.async.commit_group;" ::: "memory");
}
template <int N>
__device__ __forceinline__ void cp_wait() {
    asm volatile("cp.async.wait_group %0;" :: "n"(N) : "memory");
}
__device__ __forceinline__ void ldsm4(uint32_t* r, uint32_t a) {
    asm volatile("ldmatrix.sync.aligned.m8n8.x4.shared.b16 {%0,%1,%2,%3}, [%4];"
                 : "=r"(r[0]), "=r"(r[1]), "=r"(r[2]), "=r"(r[3]) : "r"(a));
}
__device__ __forceinline__ void ldsm4t(uint32_t* r, uint32_t a) {
    asm volatile("ldmatrix.sync.aligned.m8n8.x4.trans.shared.b16 {%0,%1,%2,%3}, [%4];"
                 : "=r"(r[0]), "=r"(r[1]), "=r"(r[2]), "=r"(r[3]) : "r"(a));
}
__device__ __forceinline__ void mma16816(float* d, const uint32_t* a, const uint32_t* b) {
    asm volatile(
        "mma.sync.aligned.m16n8k16.row.col.f32.f16.f16.f32 "
        "{%0,%1,%2,%3}, {%4,%5,%6,%7}, {%8,%9}, {%0,%1,%2,%3};"
        : "+f"(d[0]), "+f"(d[1]), "+f"(d[2]), "+f"(d[3])
        : "r"(a[0]), "r"(a[1]), "r"(a[2]), "r"(a[3]), "r"(b[0]), "r"(b[1]));
}
__device__ __forceinline__ uint32_t packh(float x, float y) {
    __half2 t = __floats2half2_rn(x, y);
    return *(uint32_t*)&t;
}
__device__ __forceinline__ float ex2f(float x) {
    float y;
    asm("ex2.approx.f32 %0, %1;" : "=f"(y) : "f"(x));
    return y;
}

// ---------------------------------------------------------------------------
// Conversions
// ---------------------------------------------------------------------------
__global__ void convert_act(const float* __restrict__ x0, const float* __restrict__ x1,
                            const float* __restrict__ x2)
{
    const int z = blockIdx.y;
    const float* x = (z == 0) ? x0 : (z == 1) ? x1 : x2;
    __half* hi = g_Ahi + (size_t)z * MROWS * DD;
    __half* lo = g_Alo + (size_t)z * MROWS * DD;

    const size_t i = (size_t)blockIdx.x * blockDim.x + threadIdx.x;
    float4 v = ((const float4*)x)[i];
    float f[4] = {v.x, v.y, v.z, v.w};
    __half h[4], l[4];
    #pragma unroll
    for (int j = 0; j < 4; j++) {
        h[j] = __float2half_rn(f[j]);
        l[j] = __float2half_rn(f[j] - __half2float(h[j]));
    }
    ((__half2*)hi)[2 * i + 0] = __half2(h[0], h[1]);
    ((__half2*)hi)[2 * i + 1] = __half2(h[2], h[3]);
    ((__half2*)lo)[2 * i + 0] = __half2(l[0], l[1]);
    ((__half2*)lo)[2 * i + 1] = __half2(l[2], l[3]);
}

// Weight transpose + round: Wt[n][k] = fp16(w[k][n])
__global__ void convert_wt(const float* __restrict__ w0, const float* __restrict__ w1,
                           const float* __restrict__ w2, const float* __restrict__ w3)
{
    __shared__ float t[32][33];
    const int z = blockIdx.z;
    const float* w = (z == 0) ? w0 : (z == 1) ? w1 : (z == 2) ? w2 : w3;
    const int nb = blockIdx.x * 32;
    const int kb = blockIdx.y * 32;

    for (int i = threadIdx.y; i < 32; i += 8)
        t[i][threadIdx.x] = w[(size_t)(kb + i) * DD + nb + threadIdx.x];
    __syncthreads();

    __half* wt = g_Wt + (size_t)z * DD * DD;
    for (int i = threadIdx.y; i < 32; i += 8)
        wt[(size_t)(nb + i) * DD + kb + threadIdx.x] = __float2half_rn(t[threadIdx.x][i]);
}

// ---------------------------------------------------------------------------
// HMMA fp16 2-term GEMM: C = (Ahi + Alo) @ W^T + bias
// CTA 128x128, K-chunk 32, 8 warps, cp.async double buffer.
// Planes per chunk: Ahi, Alo (rows=mBase), W (rows=nBase). 64 MMAs/warp/chunk.
// mode 0: QKV. epilogue -> fp16 hi/lo head-split g_Ph/g_Pl; z==0 scaled QSCALE.
// mode 1: O-proj. reads g_Ohi/g_Olo, fp32 row-major to outExt.
// ---------------------------------------------------------------------------
#define PLANE_BYTES 10240           // 128 * 80
#define BUF_BYTES   (3 * PLANE_BYTES)
#define GEMM_SMEM   (2 * BUF_BYTES) // 61440

__global__ __launch_bounds__(256, 1)
void gemm_tc(const float* __restrict__ bias0, const float* __restrict__ bias1,
             const float* __restrict__ bias2, float* __restrict__ outExt, int mode)
{
    extern __shared__ __align__(128) char smem[];
    const uint32_t smemA = smem_u32(smem);

    const int tid  = threadIdx.x;
    const int wid  = tid >> 5;
    const int lane = tid & 31;
    const int wm   = wid >> 1;
    const int wn   = wid & 1;
    const int z    = blockIdx.z;
    const int mBase = blockIdx.x * 128;
    const int nBase = blockIdx.y * 128;

    const __half* Ahi = (mode == 0) ? (g_Ahi + (size_t)z * MROWS * DD) : g_Ohi;
    const __half* Alo = (mode == 0) ? (g_Alo + (size_t)z * MROWS * DD) : g_Olo;
    const int widx = (mode == 0) ? z : 3;
    const __half* W = g_Wt + (size_t)widx * DD * DD;
    const float* bias = (z == 0) ? bias0 : (z == 1) ? bias1 : bias2;

    const __half* srcs[3] = {Ahi, Alo, W};

    auto load_chunk = [&](int buf, int k0) {
        char* bb = smem + buf * BUF_BYTES;
        #pragma unroll
        for (int it = 0; it < 6; it++) {
            const int idx = it * 256 + tid;      // 0..1535
            const int p   = idx >> 9;            // 0,1 = A planes; 2 = W
            const int r   = idx & 511;
            const int row = r >> 2;
            const int seg = r & 3;
            const int rowBase = (p < 2) ? mBase : nBase;
            const __half* g = srcs[p] + (size_t)(rowBase + row) * DD + k0 + seg * 8;
            cp_async16(smem_u32(bb + p * PLANE_BYTES + row * 80 + seg * 16), g);
        }
    };

    float acc[2][8][4];
    #pragma unroll
    for (int t = 0; t < 2; t++)
        #pragma unroll
        for (int n = 0; n < 8; n++)
            #pragma unroll
            for (int j = 0; j < 4; j++) acc[t][n][j] = 0.f;

    const int aRow = lane & 15;
    const int aCol = (lane >> 4) * 16;
    const int bRow = (lane & 7) + ((lane >> 4) << 3);
    const int bCol = ((lane >> 3) & 1) * 16;

    const int NC = DD / 32;

    load_chunk(0, 0);
    cp_commit();

    for (int c = 0; c < NC; c++) {
        const int buf = c & 1;
        if (c + 1 < NC) {
            load_chunk(buf ^ 1, (c + 1) * 32);
            cp_commit();
            cp_wait<1>();
        } else {
            cp_wait<0>();
        }
        __syncthreads();

        const uint32_t base = smemA + buf * BUF_BYTES;
        #pragma unroll
        for (int s = 0; s < 2; s++) {
            uint32_t ah[2][4], al[2][4], bh[8][2];
            #pragma unroll
            for (int t = 0; t < 2; t++) {
                const uint32_t addr = base + (wm * 32 + t * 16 + aRow) * 80 + s * 32 + aCol;
                ldsm4(ah[t], addr);
                ldsm4(al[t], addr + PLANE_BYTES);
            }
            #pragma unroll
            for (int bt = 0; bt < 4; bt++) {
                const uint32_t addr = base + 2 * PLANE_BYTES
                                    + (wn * 64 + bt * 16 + bRow) * 80 + s * 32 + bCol;
                uint32_t r4[4];
                ldsm4(r4, addr);
                bh[bt * 2][0] = r4[0]; bh[bt * 2][1] = r4[1];
                bh[bt * 2 + 1][0] = r4[2]; bh[bt * 2 + 1][1] = r4[3];
            }
            #pragma unroll
            for (int t = 0; t < 2; t++)
                #pragma unroll
                for (int n = 0; n < 8; n++) {
                    mma16816(acc[t][n], ah[t], bh[n]);   // Ahi * W
                    mma16816(acc[t][n], al[t], bh[n]);   // Alo * W
                }
        }
        __syncthreads();
    }

    // ---- epilogue ----
    const int rBase = mBase + wm * 32 + (lane >> 2);
    const int cBase = nBase + wn * 64 + (lane & 3) * 2;
    const float csc = (mode == 0 && z == 0) ? QSCALE : 1.0f;
    __half* ph = g_Ph + (size_t)z * BB * HH * SS * DK;
    __half* pl = g_Pl + (size_t)z * BB * HH * SS * DK;

    #pragma unroll
    for (int t = 0; t < 2; t++) {
        #pragma unroll
        for (int n = 0; n < 8; n++) {
            const int col = cBase + n * 8;
            const float b0v = bias[col];
            const float b1v = bias[col + 1];
            #pragma unroll
            for (int half = 0; half < 2; half++) {
                const int row = rBase + t * 16 + half * 8;
                float v0 = (acc[t][n][half * 2 + 0] + b0v) * csc;
                float v1 = (acc[t][n][half * 2 + 1] + b1v) * csc;
                if (mode == 0) {
                    const int b = row >> 11;
                    const int s = row & 2047;
                    const int h = col >> 6;
                    const int dk = col & 63;
                    const size_t o = (((size_t)(b * HH + h)) * SS + s) * DK + dk;
                    __half h0 = __float2half_rn(v0);
                    __half h1 = __float2half_rn(v1);
                    *(__half2*)&ph[o] = __half2(h0, h1);
                    *(__half2*)&pl[o] = __half2(
                        __float2half_rn(v0 - __half2float(h0)),
                        __float2half_rn(v1 - __half2float(h1)));
                } else {
                    float2 v; v.x = v0; v.y = v1;
                    *(float2*)&outExt[(size_t)row * DD + col] = v;
                }
            }
        }
    }
}

// ---------------------------------------------------------------------------
// Tensor-core flash attention, fp16 2-term.
// Q split (hi/lo regs, exact); K, V single fp16 plane.
// grid=(S/128, H, B), block=256 (8 warps, 16 q-rows each). Key tile 64.
// Smem: 2 planes x 64 rows x 144B per buf, double buffered = 36864 B.
// ---------------------------------------------------------------------------
#define ARS    144                  // attn smem row stride (bytes)
#define APLANE (64 * ARS)           // 9216
#define ABUF   (2 * APLANE)         // 18432
#define ATTN_SMEM (2 * ABUF)        // 36864

__global__ __launch_bounds__(256, 1)
void attn_tc()
{
    extern __shared__ __align__(128) char smem[];
    const uint32_t smemA = smem_u32(smem);

    const int tid  = threadIdx.x;
    const int wid  = tid >> 5;
    const int lane = tid & 31;
    const int b = blockIdx.z;
    const int h = blockIdx.y;
    const int qBase = blockIdx.x * 128;

    const size_t hb = ((size_t)(b * HH + h)) * SS * DK;
    const size_t PS = (size_t)BB * HH * SS * DK;
    const __half* Qh = g_Ph + hb;
    const __half* Ql = g_Pl + hb;
    const __half* Kh = g_Ph + PS + hb;
    const __half* Vh = g_Ph + 2 * PS + hb;

    // ---- stage Q (128 rows x 64 dk, hi+lo) through smem, load to regs ----
    {
        #pragma unroll
        for (int it = 0; it < 8; it++) {
            const int idx = it * 256 + tid;        // 0..2047
            const int p   = idx >> 10;             // 0=hi 1=lo
            const int r   = idx & 1023;
            const int row = r >> 3;
            const int seg = r & 7;
            const __half* g = (p ? Ql : Qh) + (size_t)(qBase + row) * DK + seg * 8;
            cp_async16(smemA + p * (128 * ARS) + row * ARS + seg * 16, g);
        }
        cp_commit();
        cp_wait<0>();
        __syncthreads();
    }

    uint32_t qh[4][4], ql[4][4];
    {
        const int aRow = lane & 15;
        const int aCol = (lane >> 4) * 16;
        #pragma unroll
        for (int s = 0; s < 4; s++) {
            const uint32_t addr = smemA + (wid * 16 + aRow) * ARS + s * 32 + aCol;
            ldsm4(qh[s], addr);
            ldsm4(ql[s], addr + 128 * ARS);
        }
    }
    __syncthreads();   // Q regs extracted; smem reusable

    // ---- K/V tile loader (single fp16 planes) ----
    auto load_kv = [&](int buf, int t0) {
        char* bb = smem + buf * ABUF;
        #pragma unroll
        for (int it = 0; it < 4; it++) {
            const int idx = it * 256 + tid;        // 0..1023
            const int p   = idx >> 9;              // 0=K 1=V
            const int r   = idx & 511;
            const int row = r >> 3;
            const int seg = r & 7;
            const __half* g = (p ? Vh : Kh) + (size_t)(t0 + row) * DK + seg * 8;
            cp_async16(smem_u32(bb + p * APLANE + row * ARS + seg * 16), g);
        }
    };

    float oacc[8][4];
    #pragma unroll
    for (int n = 0; n < 8; n++)
        #pragma unroll
        for (int j = 0; j < 4; j++) oacc[n][j] = 0.f;
    float m0 = -1e30f, m1 = -1e30f, l0 = 0.f, l1 = 0.f;

    const int bRow = (lane & 7) + ((lane >> 4) << 3);
    const int bCol = ((lane >> 3) & 1) * 16;
    const int vRow = lane & 15;
    const int vCol = (lane >> 4) * 16;

    load_kv(0, 0);
    cp_commit();

    const int NT = SS / 64;   // 32 key tiles

    for (int t = 0; t < NT; t++) {
        const int buf = t & 1;
        if (t + 1 < NT) {
            load_kv(buf ^ 1, (t + 1) * 64);
            cp_commit();
            cp_wait<1>();
        } else {
            cp_wait<0>();
        }
        __syncthreads();

        const uint32_t kbase = smemA + buf * ABUF;
        const uint32_t vbase = kbase + APLANE;

        // ---- S = Q K^T (fp16 2-term: qh*K + ql*K) ----
        float sc[8][4];
        #pragma unroll
        for (int n = 0; n < 8; n++)
            #pragma unroll
            for (int j = 0; j < 4; j++) sc[n][j] = 0.f;

        #pragma unroll
        for (int s = 0; s < 4; s++) {
            uint32_t bh[8][2];
            #pragma unroll
            for (int bt = 0; bt < 4; bt++) {
                const uint32_t addr = kbase + (bt * 16 + bRow) * ARS + s * 32 + bCol;
                uint32_t r4[4];
                ldsm4(r4, addr);
                bh[bt * 2][0] = r4[0]; bh[bt * 2][1] = r4[1];
                bh[bt * 2 + 1][0] = r4[2]; bh[bt * 2 + 1][1] = r4[3];
            }
            #pragma unroll
            for (int n = 0; n < 8; n++) {
                mma16816(sc[n], qh[s], bh[n]);
                mma16816(sc[n], ql[s], bh[n]);
            }
        }

        // ---- online softmax (base 2, single-MUFU exp) ----
        float t0v = -1e30f, t1v = -1e30f;
        #pragma unroll
        for (int n = 0; n < 8; n++) {
            t0v = fmaxf(t0v, fmaxf(sc[n][0], sc[n][1]));
            t1v = fmaxf(t1v, fmaxf(sc[n][2], sc[n][3]));
        }
        t0v = fmaxf(t0v, __shfl_xor_sync(0xffffffffu, t0v, 1));
        t0v = fmaxf(t0v, __shfl_xor_sync(0xffffffffu, t0v, 2));
        t1v = fmaxf(t1v, __shfl_xor_sync(0xffffffffu, t1v, 1));
        t1v = fmaxf(t1v, __shfl_xor_sync(0xffffffffu, t1v, 2));

        const float nm0 = fmaxf(m0, t0v);
        const float nm1 = fmaxf(m1, t1v);
        const float c0 = ex2f(m0 - nm0);
        const float c1 = ex2f(m1 - nm1);
        m0 = nm0; m1 = nm1;
        l0 *= c0;  l1 *= c1;
        #pragma unroll
        for (int n = 0; n < 8; n++) {
            oacc[n][0] *= c0; oacc[n][1] *= c0;
            oacc[n][2] *= c1; oacc[n][3] *= c1;
        }

        float rs0 = 0.f, rs1 = 0.f;
        #pragma unroll
        for (int n = 0; n < 8; n++) {
            sc[n][0] = ex2f(sc[n][0] - nm0);
            sc[n][1] = ex2f(sc[n][1] - nm0);
            sc[n][2] = ex2f(sc[n][2] - nm1);
            sc[n][3] = ex2f(sc[n][3] - nm1);
            rs0 += sc[n][0] + sc[n][1];
            rs1 += sc[n][2] + sc[n][3];
        }
        rs0 += __shfl_xor_sync(0xffffffffu, rs0, 1);
        rs0 += __shfl_xor_sync(0xffffffffu, rs0, 2);
        rs1 += __shfl_xor_sync(0xffffffffu, rs1, 1);
        rs1 += __shfl_xor_sync(0xffffffffu, rs1, 2);
        l0 += rs0; l1 += rs1;

        // ---- O += P V (P split hi/lo fp16 exact; V single fp16) ----
        #pragma unroll
        for (int j = 0; j < 4; j++) {
            float p00 = sc[2*j][0],   p01 = sc[2*j][1];
            float p02 = sc[2*j][2],   p03 = sc[2*j][3];
            float p10 = sc[2*j+1][0], p11 = sc[2*j+1][1];
            float p12 = sc[2*j+1][2], p13 = sc[2*j+1][3];
            uint32_t aph[4], apl[4];
            aph[0] = packh(p00, p01); aph[1] = packh(p02, p03);
            aph[2] = packh(p10, p11); aph[3] = packh(p12, p13);
            {
                __half2 h0 = *(__half2*)&aph[0];
                __half2 h1 = *(__half2*)&aph[1];
                __half2 h2 = *(__half2*)&aph[2];
                __half2 h3 = *(__half2*)&aph[3];
                apl[0] = packh(p00 - __half2float(h0.x), p01 - __half2float(h0.y));
                apl[1] = packh(p02 - __half2float(h1.x), p03 - __half2float(h1.y));
                apl[2] = packh(p10 - __half2float(h2.x), p11 - __half2float(h2.y));
                apl[3] = packh(p12 - __half2float(h3.x), p13 - __half2float(h3.y));
            }

            uint32_t vb[8][2];
            #pragma unroll
            for (int d = 0; d < 4; d++) {
                const uint32_t addr = vbase + (j * 16 + vRow) * ARS + d * 32 + vCol;
                uint32_t r4[4];
                ldsm4t(r4, addr);
                vb[d * 2][0] = r4[0]; vb[d * 2][1] = r4[1];
                vb[d * 2 + 1][0] = r4[2]; vb[d * 2 + 1][1] = r4[3];
            }
            #pragma unroll
            for (int n = 0; n < 8; n++) {
                mma16816(oacc[n], aph, vb[n]);
                mma16816(oacc[n], apl, vb[n]);
            }
        }
        __syncthreads();
    }

    // ---- epilogue: normalize, split fp16 hi/lo, write [B,S,D] ----
    const float inv0 = 1.f / l0;
    const float inv1 = 1.f / l1;
    const int s0 = qBase + wid * 16 + (lane >> 2);
    const int s1 = s0 + 8;
    #pragma unroll
    for (int n = 0; n < 8; n++) {
        const int col = h * 64 + n * 8 + (lane & 3) * 2;
        {
            float v0 = oacc[n][0] * inv0, v1 = oacc[n][1] * inv0;
            __half h0 = __float2half_rn(v0);
            __half h1 = __float2half_rn(v1);
            const size_t o = ((size_t)(b * SS + s0)) * DD + col;
            *(__half2*)&g_Ohi[o] = __half2(h0, h1);
            *(__half2*)&g_Olo[o] = __half2(
                __float2half_rn(v0 - __half2float(h0)),
                __float2half_rn(v1 - __half2float(h1)));
        }
        {
            float v0 = oacc[n][2] * inv1, v1 = oacc[n][3] * inv1;
            __half h0 = __float2half_rn(v0);
            __half h1 = __float2half_rn(v1);
            const size_t o = ((size_t)(b * SS + s1)) * DD + col;
            *(__half2*)&g_Ohi[o] = __half2(h0, h1);
            *(__half2*)&g_Olo[o] = __half2(
                __float2half_rn(v0 - __half2float(h0)),
                __float2half_rn(v1 - __half2float(h1)));
        }
    }
}

// ---------------------------------------------------------------------------
extern "C" void kernel_launch(void* const* d_in, const int* in_sizes, int n_in,
                              void* d_out, int out_size)
{
    const float* q  = (const float*)d_in[0];
    const float* k  = (const float*)d_in[1];
    const float* v  = (const float*)d_in[2];
    const float* wq = (const float*)d_in[3];
    const float* bq = (const float*)d_in[4];
    const float* wk = (const float*)d_in[5];
    const float* bk = (const float*)d_in[6];
    const float* wv = (const float*)d_in[7];
    const float* bv = (const float*)d_in[8];
    const float* wo = (const float*)d_in[9];
    const float* bo = (const float*)d_in[10];
    float* out = (float*)d_out;

    cudaFuncSetAttribute(gemm_tc, cudaFuncAttributeMaxDynamicSharedMemorySize, GEMM_SMEM);
    cudaFuncSetAttribute(attn_tc, cudaFuncAttributeMaxDynamicSharedMemorySize, ATTN_SMEM);

    // 1) Split activations to fp16 hi/lo; transpose+round weights to fp16
    convert_act<<<dim3(MROWS * DD / 4 / 256, 3), 256>>>(q, k, v);
    convert_wt<<<dim3(32, 32, 4), dim3(32, 8)>>>(wq, wk, wv, wo);

    // 2) QKV projections -> fp16 hi/lo head-split (Q pre-scaled by 0.125*log2e)
    gemm_tc<<<dim3(MROWS / 128, DD / 128, 3), 256, GEMM_SMEM>>>(bq, bk, bv, nullptr, 0);

    // 3) Tensor-core flash attention -> g_Ohi/g_Olo
    attn_tc<<<dim3(SS / 128, HH, BB), 256, ATTN_SMEM>>>();

    // 4) O projection
    gemm_tc<<<dim3(MROWS / 128, DD / 128, 1), 256, GEMM_SMEM>>>(bo, bo, bo, out, 1);
}